// round 10
// baseline (speedup 1.0000x reference)
#include <cuda_runtime.h>
#include <math.h>

#define B_    8
#define C_    192
#define HW_   16384
#define CHW_  3145728
#define NTOT_ 25165824
#define NQC_  8193           // coarse table entries used (stride-8 grid + endpoint)
#define NQCP_ 8200           // padded per-channel stride (16B-aligned rows)

typedef unsigned long long u64;

// ---------------- device scratch (no allocations allowed) ----------------
__device__ unsigned g_min_enc[B_];
__device__ unsigned g_max_enc[B_];
__device__ float    g_qs[B_];          // per-sample quantize scale
__device__ float    g_qo[B_];          // per-sample quantize offset
__device__ float    g_cw[C_ * 58];     // packed per-channel transformed weights
__device__ __align__(16) float g_likc[C_ * NQCP_];  // coarse lik table (~6.3MB)

// monotone float<->uint encoding for atomic min/max
__device__ __forceinline__ unsigned fenc(float f) {
    unsigned u = __float_as_uint(f);
    return (u & 0x80000000u) ? ~u : (u | 0x80000000u);
}
__device__ __forceinline__ float fdec(unsigned u) {
    return (u & 0x80000000u) ? __uint_as_float(u ^ 0x80000000u)
                             : __uint_as_float(~u);
}

// ---------------- kernel 1: weight prep + reduction-cell init ----------------
__device__ __forceinline__ float softplus_acc(float v) {
    return fmaxf(v, 0.0f) + log1pf(expf(-fabsf(v)));
}

__global__ void k_prep_w(const float* __restrict__ m0, const float* __restrict__ b0,
                         const float* __restrict__ m1, const float* __restrict__ b1,
                         const float* __restrict__ m2, const float* __restrict__ b2,
                         const float* __restrict__ m3, const float* __restrict__ b3,
                         const float* __restrict__ m4, const float* __restrict__ b4,
                         const float* __restrict__ f0, const float* __restrict__ f1,
                         const float* __restrict__ f2, const float* __restrict__ f3) {
    int c = threadIdx.x;
    if (c < C_) {
        float* w = &g_cw[c * 58];
        #pragma unroll
        for (int j = 0; j < 3; j++) {
            w[0 + j]  = softplus_acc(m0[c * 3 + j]);
            w[3 + j]  = b0[c * 3 + j];
            w[6 + j]  = tanhf(f0[c * 3 + j]);
            w[18 + j] = b1[c * 3 + j];
            w[21 + j] = tanhf(f1[c * 3 + j]);
            w[33 + j] = b2[c * 3 + j];
            w[36 + j] = tanhf(f2[c * 3 + j]);
            w[48 + j] = b3[c * 3 + j];
            w[51 + j] = tanhf(f3[c * 3 + j]);
            w[54 + j] = softplus_acc(m4[c * 3 + j]);
        }
        #pragma unroll
        for (int j = 0; j < 9; j++) {
            w[9  + j] = softplus_acc(m1[c * 9 + j]);
            w[24 + j] = softplus_acc(m2[c * 9 + j]);
            w[39 + j] = softplus_acc(m3[c * 9 + j]);
        }
        w[57] = b4[c];
    }
    if (threadIdx.x < B_) {
        g_min_enc[threadIdx.x] = 0xFFFFFFFFu;
        g_max_enc[threadIdx.x] = 0u;
    }
}

// ---------------- kernel 3: quantize params (after fused minmax) -------------
__global__ void k_prep_q() {
    int s = threadIdx.x;
    if (s < B_) {
        float mn = fdec(g_min_enc[s]);
        float mx = fdec(g_max_enc[s]);
        float denom = (mx - mn) + 1e-12f;
        float qs = __fdiv_rn(65535.0f, denom);   // q = rint((x - mn) * qs)
        g_qs[s] = qs;
        g_qo[s] = -mn * qs;
    }
}

// ---------------- packed f32x2 helpers (sm_103a FFMA2) ----------------
__device__ __forceinline__ u64 pk2(float a, float b) {
    u64 r; asm("mov.b64 %0, {%1, %2};" : "=l"(r) : "f"(a), "f"(b)); return r;
}
__device__ __forceinline__ void unpk(u64 v, float& a, float& b) {
    asm("mov.b64 {%0, %1}, %2;" : "=f"(a), "=f"(b) : "l"(v));
}
__device__ __forceinline__ u64 fma2(u64 a, u64 b, u64 c) {
    u64 d; asm("fma.rn.f32x2 %0, %1, %2, %3;" : "=l"(d) : "l"(a), "l"(b), "l"(c));
    return d;
}
// gate: y = z + t * tanh(z), tanh via f16x2 MUFU (both lanes in one op)
__device__ __forceinline__ u64 gate2(u64 z, u64 t2) {
    float zl, zu;
    unpk(z, zl, zu);
    unsigned h;
    asm("cvt.rn.f16x2.f32 %0, %1, %2;" : "=r"(h) : "f"(zu), "f"(zl)); // lo=zl, hi=zu
    asm("tanh.approx.f16x2 %0, %1;" : "=r"(h) : "r"(h));
    float tl, tu;
    asm("{\n\t.reg .b16 lo, hi;\n\tmov.b32 {lo, hi}, %2;\n\t"
        "cvt.f32.f16 %0, lo;\n\tcvt.f32.f16 %1, hi;\n\t}"
        : "=f"(tl), "=f"(tu) : "r"(h));
    return fma2(t2, pk2(tl, tu), z);
}
__device__ __forceinline__ float sigf(float v) {
    return __fdividef(1.0f, 1.0f + __expf(-v));
}

// dual-q packed MLP: va/vb = packed (lower, upper) for two q's.
__device__ __forceinline__ void mlp_dual(u64 va, u64 vb, const u64* __restrict__ sW,
                                         u64& ra, u64& rb) {
    u64 w0 = sW[0], w1 = sW[1], w2 = sW[2];
    u64 bb0 = sW[3], bb1 = sW[4], bb2 = sW[5];
    u64 ya0 = fma2(w0, va, bb0), yb0 = fma2(w0, vb, bb0);
    u64 ya1 = fma2(w1, va, bb1), yb1 = fma2(w1, vb, bb1);
    u64 ya2 = fma2(w2, va, bb2), yb2 = fma2(w2, vb, bb2);
    u64 t0 = sW[6], t1 = sW[7], t2 = sW[8];
    ya0 = gate2(ya0, t0); yb0 = gate2(yb0, t0);
    ya1 = gate2(ya1, t1); yb1 = gate2(yb1, t1);
    ya2 = gate2(ya2, t2); yb2 = gate2(yb2, t2);
    #pragma unroll
    for (int L = 0; L < 3; L++) {
        const u64* Wl = sW + 9 + L * 15;
        u64 m0 = Wl[0], m1 = Wl[1], m2 = Wl[2];
        u64 m3 = Wl[3], m4 = Wl[4], m5 = Wl[5];
        u64 m6 = Wl[6], m7 = Wl[7], m8 = Wl[8];
        u64 c0 = Wl[9], c1 = Wl[10], c2 = Wl[11];
        u64 za0 = fma2(m0, ya0, fma2(m1, ya1, fma2(m2, ya2, c0)));
        u64 zb0 = fma2(m0, yb0, fma2(m1, yb1, fma2(m2, yb2, c0)));
        u64 za1 = fma2(m3, ya0, fma2(m4, ya1, fma2(m5, ya2, c1)));
        u64 zb1 = fma2(m3, yb0, fma2(m4, yb1, fma2(m5, yb2, c1)));
        u64 za2 = fma2(m6, ya0, fma2(m7, ya1, fma2(m8, ya2, c2)));
        u64 zb2 = fma2(m6, yb0, fma2(m7, yb1, fma2(m8, yb2, c2)));
        u64 g0 = Wl[12], g1 = Wl[13], g2 = Wl[14];
        ya0 = gate2(za0, g0); yb0 = gate2(zb0, g0);
        ya1 = gate2(za1, g1); yb1 = gate2(zb1, g1);
        ya2 = gate2(za2, g2); yb2 = gate2(zb2, g2);
    }
    u64 f0 = sW[54], f1 = sW[55], f2 = sW[56], f3 = sW[57];
    ra = fma2(f0, ya0, fma2(f1, ya1, fma2(f2, ya2, f3)));
    rb = fma2(f0, yb0, fma2(f1, yb1, fma2(f2, yb2, f3)));
}

// ---------------- kernel 2: FUSED coarse table + per-sample min/max ----------
// 2816 blocks, interleaved roles per group of 88: 24 table-blocks (compute) +
// 64 minmax-blocks (DRAM) -> both resident, pipes overlap.
__global__ void __launch_bounds__(256) k_mm_table(const float* __restrict__ x) {
    const int grp = blockIdx.x / 88;
    const int r   = blockIdx.x % 88;
    __shared__ float smn[8], smx[8];

    if (r < 24) {
        // ----- table role: table_id in [0, 768) -----
        __shared__ u64 sW[58];
        const int tb = grp * 24 + r;
        const int c  = tb >> 2;
        const int jb = tb & 3;
        const int e0 = (jb << 11) + threadIdx.x;

        if (threadIdx.x < 58) {
            float wv = g_cw[c * 58 + threadIdx.x];
            sW[threadIdx.x] = pk2(wv, wv);
        }
        __syncthreads();

        float* lt = g_likc + (size_t)c * NQCP_;
        const float rq = 1.0f / 65535.0f;

        #pragma unroll
        for (int k = 0; k < 4; k++) {
            int ea = e0 + k * 256;
            int eb = ea + 1024;
            float xa = (float)(ea << 3) * rq;
            float xb = (float)(eb << 3) * rq;
            u64 la, lb;
            mlp_dual(pk2(xa - 0.5f, xa + 0.5f), pk2(xb - 0.5f, xb + 0.5f), sW, la, lb);
            float lal, lau, lbl, lbu;
            unpk(la, lal, lau);
            unpk(lb, lbl, lbu);
            lt[ea] = fmaxf(sigf(lau) - sigf(lal), 1e-9f);
            lt[eb] = fmaxf(sigf(lbu) - sigf(lbl), 1e-9f);
        }
        if (jb == 3 && threadIdx.x == 0) {
            float xe = 65536.0f * rq;
            u64 le, ldum;
            u64 v = pk2(xe - 0.5f, xe + 0.5f);
            mlp_dual(v, v, sW, le, ldum);
            float ll, lu;
            unpk(le, ll, lu);
            lt[8192] = fmaxf(sigf(lu) - sigf(ll), 1e-9f);
        }
    } else {
        // ----- minmax role: mm_id in [0, 2048) -----
        const int mm = grp * 64 + (r - 24);
        const int s  = mm >> 8;
        const int jb = mm & 255;
        const float4* xp = reinterpret_cast<const float4*>(x + (size_t)s * CHW_)
                           + (size_t)jb * 3072;

        float mn = __int_as_float(0x7f800000);
        float mx = -mn;
        for (int i = threadIdx.x; i < 3072; i += 256) {
            float4 v = __ldcs(xp + i);
            mn = fminf(mn, fminf(fminf(v.x, v.y), fminf(v.z, v.w)));
            mx = fmaxf(mx, fmaxf(fmaxf(v.x, v.y), fmaxf(v.z, v.w)));
        }
        #pragma unroll
        for (int o = 16; o > 0; o >>= 1) {
            mn = fminf(mn, __shfl_xor_sync(0xffffffffu, mn, o));
            mx = fmaxf(mx, __shfl_xor_sync(0xffffffffu, mx, o));
        }
        int w = threadIdx.x >> 5, l = threadIdx.x & 31;
        if (l == 0) { smn[w] = mn; smx[w] = mx; }
        __syncthreads();
        if (threadIdx.x == 0) {
            mn = smn[0]; mx = smx[0];
            #pragma unroll
            for (int i = 1; i < 8; i++) { mn = fminf(mn, smn[i]); mx = fmaxf(mx, smx[i]); }
            atomicMin(&g_min_enc[s], fenc(mn));
            atomicMax(&g_max_enc[s], fenc(mx));
        }
    }
}

// ---------------- kernel 4: quantize + interpolated gather ----------------
// 1536 blocks = (s,c) planes; 256 threads; 16384 elems/block, 8 pipelined
// chunks of 8 elems/thread. Whole coarse channel table in smem -> no misses.
__global__ void __launch_bounds__(256, 5) k_gather(const float* __restrict__ x,
                                                   float* __restrict__ out) {
    extern __shared__ float sw[];
    const int c = blockIdx.x % C_;
    const int s = blockIdx.x / C_;
    const size_t base = (size_t)s * CHW_ + (size_t)c * HW_;

    const float qs = g_qs[s];
    const float qo = g_qo[s];
    const int t = threadIdx.x;
    const float rq = 1.0f / 65535.0f;

    const float4* xp = reinterpret_cast<const float4*>(x + base);
    float4* ov = reinterpret_cast<float4*>(out + base);
    float4* lv = reinterpret_cast<float4*>(out + NTOT_ + base);

    // prefetch chunk 0 (streaming)
    float4 va = __ldcs(xp + t);
    float4 vb = __ldcs(xp + t + 256);

    // stage full coarse channel table into smem (2050 uint4 = 8200 floats)
    {
        const uint4* src = reinterpret_cast<const uint4*>(g_likc + (size_t)c * NQCP_);
        uint4* dst = reinterpret_cast<uint4*>(sw);
        #pragma unroll
        for (int i = 0; i < 9; i++) {
            int idx = t + i * 256;
            if (idx < 2050) dst[idx] = __ldg(src + idx);
        }
    }
    __syncthreads();

    #pragma unroll
    for (int k = 0; k < 8; k++) {
        float4 v0 = va, v1 = vb;
        if (k < 7) {
            va = __ldcs(xp + (k + 1) * 512 + t);
            vb = __ldcs(xp + (k + 1) * 512 + t + 256);
        }
        int q[8];
        q[0] = min(max(__float2int_rn(fmaf(v0.x, qs, qo)), 0), 65535);
        q[1] = min(max(__float2int_rn(fmaf(v0.y, qs, qo)), 0), 65535);
        q[2] = min(max(__float2int_rn(fmaf(v0.z, qs, qo)), 0), 65535);
        q[3] = min(max(__float2int_rn(fmaf(v0.w, qs, qo)), 0), 65535);
        q[4] = min(max(__float2int_rn(fmaf(v1.x, qs, qo)), 0), 65535);
        q[5] = min(max(__float2int_rn(fmaf(v1.y, qs, qo)), 0), 65535);
        q[6] = min(max(__float2int_rn(fmaf(v1.z, qs, qo)), 0), 65535);
        q[7] = min(max(__float2int_rn(fmaf(v1.w, qs, qo)), 0), 65535);

        float4 o0, o1;
        o0.x = (float)q[0] * rq; o0.y = (float)q[1] * rq;
        o0.z = (float)q[2] * rq; o0.w = (float)q[3] * rq;
        o1.x = (float)q[4] * rq; o1.y = (float)q[5] * rq;
        o1.z = (float)q[6] * rq; o1.w = (float)q[7] * rq;
        __stcs(ov + k * 512 + t, o0);
        __stcs(ov + k * 512 + t + 256, o1);

        float l[8];
        #pragma unroll
        for (int j = 0; j < 8; j++) {
            int i0 = q[j] >> 3;
            float f = (float)(q[j] & 7) * 0.125f;
            float a = sw[i0];
            float b = sw[i0 + 1];
            l[j] = fmaf(b - a, f, a);
        }
        float4 l0, l1;
        l0.x = l[0]; l0.y = l[1]; l0.z = l[2]; l0.w = l[3];
        l1.x = l[4]; l1.y = l[5]; l1.z = l[6]; l1.w = l[7];
        __stcs(lv + k * 512 + t, l0);
        __stcs(lv + k * 512 + t + 256, l1);
    }
}

// ---------------- host launcher ----------------
extern "C" void kernel_launch(void* const* d_in, const int* in_sizes, int n_in,
                              void* d_out, int out_size) {
    const float* x = (const float*)d_in[0];
    const float *m[5], *bb[5], *ff[4];
    if (n_in >= 15 && in_sizes[2] == 1728) {
        for (int i = 0; i < 5; i++) { m[i]  = (const float*)d_in[1 + i];
                                      bb[i] = (const float*)d_in[6 + i]; }
        for (int i = 0; i < 4; i++)   ff[i] = (const float*)d_in[11 + i];
    } else {
        for (int i = 0; i < 5; i++) { m[i]  = (const float*)d_in[1 + 2 * i];
                                      bb[i] = (const float*)d_in[2 + 2 * i]; }
        for (int i = 0; i < 4; i++)   ff[i] = (const float*)d_in[11 + i];
    }
    float* out = (float*)d_out;

    static int smem_set = 0;
    if (!smem_set) {
        cudaFuncSetAttribute(k_gather, cudaFuncAttributeMaxDynamicSharedMemorySize,
                             2050 * 16);
        smem_set = 1;
    }

    k_prep_w<<<1, 192>>>(m[0], bb[0], m[1], bb[1], m[2], bb[2], m[3], bb[3],
                         m[4], bb[4], ff[0], ff[1], ff[2], ff[3]);
    k_mm_table<<<2816, 256>>>(x);
    k_prep_q<<<1, 32>>>();
    k_gather<<<1536, 256, 2050 * 16>>>(x, out);
}

// round 11
// speedup vs baseline: 1.2111x; 1.2111x over previous
#include <cuda_runtime.h>
#include <math.h>

#define B_    8
#define C_    192
#define HW_   16384
#define CHW_  3145728
#define NTOT_ 25165824
#define NQC_  8193           // coarse table entries used (stride-8 grid + endpoint)
#define NQCP_ 8200           // padded per-channel stride (16B-aligned rows)

typedef unsigned long long u64;

// ---------------- device scratch (no allocations allowed) ----------------
__device__ unsigned g_min_enc[B_];
__device__ unsigned g_max_enc[B_];
__device__ float    g_qs[B_];          // per-sample quantize scale
__device__ float    g_qo[B_];          // per-sample quantize offset
__device__ float    g_cw[C_ * 58];     // packed per-channel transformed weights
__device__ __align__(16) float g_likc[C_ * NQCP_];  // coarse lik table (~6.3MB)

// monotone float<->uint encoding for atomic min/max
__device__ __forceinline__ unsigned fenc(float f) {
    unsigned u = __float_as_uint(f);
    return (u & 0x80000000u) ? ~u : (u | 0x80000000u);
}
__device__ __forceinline__ float fdec(unsigned u) {
    return (u & 0x80000000u) ? __uint_as_float(u ^ 0x80000000u)
                             : __uint_as_float(~u);
}

// ---------------- kernel: weight prep + reduction-cell init ----------------
__device__ __forceinline__ float softplus_acc(float v) {
    return fmaxf(v, 0.0f) + log1pf(expf(-fabsf(v)));
}

__global__ void k_prep_w(const float* __restrict__ m0, const float* __restrict__ b0,
                         const float* __restrict__ m1, const float* __restrict__ b1,
                         const float* __restrict__ m2, const float* __restrict__ b2,
                         const float* __restrict__ m3, const float* __restrict__ b3,
                         const float* __restrict__ m4, const float* __restrict__ b4,
                         const float* __restrict__ f0, const float* __restrict__ f1,
                         const float* __restrict__ f2, const float* __restrict__ f3) {
    int c = threadIdx.x;
    if (c < C_) {
        float* w = &g_cw[c * 58];
        #pragma unroll
        for (int j = 0; j < 3; j++) {
            w[0 + j]  = softplus_acc(m0[c * 3 + j]);
            w[3 + j]  = b0[c * 3 + j];
            w[6 + j]  = tanhf(f0[c * 3 + j]);
            w[18 + j] = b1[c * 3 + j];
            w[21 + j] = tanhf(f1[c * 3 + j]);
            w[33 + j] = b2[c * 3 + j];
            w[36 + j] = tanhf(f2[c * 3 + j]);
            w[48 + j] = b3[c * 3 + j];
            w[51 + j] = tanhf(f3[c * 3 + j]);
            w[54 + j] = softplus_acc(m4[c * 3 + j]);
        }
        #pragma unroll
        for (int j = 0; j < 9; j++) {
            w[9  + j] = softplus_acc(m1[c * 9 + j]);
            w[24 + j] = softplus_acc(m2[c * 9 + j]);
            w[39 + j] = softplus_acc(m3[c * 9 + j]);
        }
        w[57] = b4[c];
    }
    if (threadIdx.x < B_) {
        g_min_enc[threadIdx.x] = 0xFFFFFFFFu;
        g_max_enc[threadIdx.x] = 0u;
    }
}

// ---------------- kernel: per-sample min/max (runs concurrent w/ table) ------
__global__ void __launch_bounds__(256) k_minmax(const float* __restrict__ x) {
    int s  = blockIdx.x >> 8;
    int jb = blockIdx.x & 255;
    const float4* xp = reinterpret_cast<const float4*>(x + (size_t)s * CHW_) + (size_t)jb * 3072;

    float mn = __int_as_float(0x7f800000);
    float mx = -mn;
    for (int i = threadIdx.x; i < 3072; i += 256) {
        float4 v = __ldcs(xp + i);
        mn = fminf(mn, fminf(fminf(v.x, v.y), fminf(v.z, v.w)));
        mx = fmaxf(mx, fmaxf(fmaxf(v.x, v.y), fmaxf(v.z, v.w)));
    }
    #pragma unroll
    for (int o = 16; o > 0; o >>= 1) {
        mn = fminf(mn, __shfl_xor_sync(0xffffffffu, mn, o));
        mx = fmaxf(mx, __shfl_xor_sync(0xffffffffu, mx, o));
    }
    __shared__ float smn[8], smx[8];
    int w = threadIdx.x >> 5, l = threadIdx.x & 31;
    if (l == 0) { smn[w] = mn; smx[w] = mx; }
    __syncthreads();
    if (threadIdx.x == 0) {
        mn = smn[0]; mx = smx[0];
        #pragma unroll
        for (int i = 1; i < 8; i++) { mn = fminf(mn, smn[i]); mx = fmaxf(mx, smx[i]); }
        atomicMin(&g_min_enc[s], fenc(mn));
        atomicMax(&g_max_enc[s], fenc(mx));
    }
}

// ---------------- kernel: quantize params (after minmax join) ----------------
__global__ void k_prep_q() {
    int s = threadIdx.x;
    if (s < B_) {
        float mn = fdec(g_min_enc[s]);
        float mx = fdec(g_max_enc[s]);
        float denom = (mx - mn) + 1e-12f;
        float qs = __fdiv_rn(65535.0f, denom);   // q = rint((x - mn) * qs)
        g_qs[s] = qs;
        g_qo[s] = -mn * qs;
    }
}

// ---------------- packed f32x2 helpers (sm_103a FFMA2) ----------------
__device__ __forceinline__ u64 pk2(float a, float b) {
    u64 r; asm("mov.b64 %0, {%1, %2};" : "=l"(r) : "f"(a), "f"(b)); return r;
}
__device__ __forceinline__ void unpk(u64 v, float& a, float& b) {
    asm("mov.b64 {%0, %1}, %2;" : "=f"(a), "=f"(b) : "l"(v));
}
__device__ __forceinline__ u64 fma2(u64 a, u64 b, u64 c) {
    u64 d; asm("fma.rn.f32x2 %0, %1, %2, %3;" : "=l"(d) : "l"(a), "l"(b), "l"(c));
    return d;
}
// gate: y = z + t * tanh(z), tanh via f16x2 MUFU (both lanes in one op)
__device__ __forceinline__ u64 gate2(u64 z, u64 t2) {
    float zl, zu;
    unpk(z, zl, zu);
    unsigned h;
    asm("cvt.rn.f16x2.f32 %0, %1, %2;" : "=r"(h) : "f"(zu), "f"(zl)); // lo=zl, hi=zu
    asm("tanh.approx.f16x2 %0, %1;" : "=r"(h) : "r"(h));
    float tl, tu;
    asm("{\n\t.reg .b16 lo, hi;\n\tmov.b32 {lo, hi}, %2;\n\t"
        "cvt.f32.f16 %0, lo;\n\tcvt.f32.f16 %1, hi;\n\t}"
        : "=f"(tl), "=f"(tu) : "r"(h));
    return fma2(t2, pk2(tl, tu), z);
}
__device__ __forceinline__ float sigf(float v) {
    return __fdividef(1.0f, 1.0f + __expf(-v));
}

// dual-q packed MLP: va/vb = packed (lower, upper) for two q's.
__device__ __forceinline__ void mlp_dual(u64 va, u64 vb, const u64* __restrict__ sW,
                                         u64& ra, u64& rb) {
    u64 w0 = sW[0], w1 = sW[1], w2 = sW[2];
    u64 bb0 = sW[3], bb1 = sW[4], bb2 = sW[5];
    u64 ya0 = fma2(w0, va, bb0), yb0 = fma2(w0, vb, bb0);
    u64 ya1 = fma2(w1, va, bb1), yb1 = fma2(w1, vb, bb1);
    u64 ya2 = fma2(w2, va, bb2), yb2 = fma2(w2, vb, bb2);
    u64 t0 = sW[6], t1 = sW[7], t2 = sW[8];
    ya0 = gate2(ya0, t0); yb0 = gate2(yb0, t0);
    ya1 = gate2(ya1, t1); yb1 = gate2(yb1, t1);
    ya2 = gate2(ya2, t2); yb2 = gate2(yb2, t2);
    #pragma unroll
    for (int L = 0; L < 3; L++) {
        const u64* Wl = sW + 9 + L * 15;
        u64 m0 = Wl[0], m1 = Wl[1], m2 = Wl[2];
        u64 m3 = Wl[3], m4 = Wl[4], m5 = Wl[5];
        u64 m6 = Wl[6], m7 = Wl[7], m8 = Wl[8];
        u64 c0 = Wl[9], c1 = Wl[10], c2 = Wl[11];
        u64 za0 = fma2(m0, ya0, fma2(m1, ya1, fma2(m2, ya2, c0)));
        u64 zb0 = fma2(m0, yb0, fma2(m1, yb1, fma2(m2, yb2, c0)));
        u64 za1 = fma2(m3, ya0, fma2(m4, ya1, fma2(m5, ya2, c1)));
        u64 zb1 = fma2(m3, yb0, fma2(m4, yb1, fma2(m5, yb2, c1)));
        u64 za2 = fma2(m6, ya0, fma2(m7, ya1, fma2(m8, ya2, c2)));
        u64 zb2 = fma2(m6, yb0, fma2(m7, yb1, fma2(m8, yb2, c2)));
        u64 g0 = Wl[12], g1 = Wl[13], g2 = Wl[14];
        ya0 = gate2(za0, g0); yb0 = gate2(zb0, g0);
        ya1 = gate2(za1, g1); yb1 = gate2(zb1, g1);
        ya2 = gate2(za2, g2); yb2 = gate2(zb2, g2);
    }
    u64 f0 = sW[54], f1 = sW[55], f2 = sW[56], f3 = sW[57];
    ra = fma2(f0, ya0, fma2(f1, ya1, fma2(f2, ya2, f3)));
    rb = fma2(f0, yb0, fma2(f1, yb1, fma2(f2, yb2, f3)));
}

// ---------------- kernel: coarse (c, e) likelihood table ----------------
// 768 blocks (4 per channel) x 256 threads; entry e covers fine q = 8e.
__global__ void __launch_bounds__(256) k_tablec() {
    __shared__ u64 sW[58];
    const int c  = blockIdx.x >> 2;
    const int jb = blockIdx.x & 3;
    const int e0 = (jb << 11) + threadIdx.x;

    if (threadIdx.x < 58) {
        float wv = g_cw[c * 58 + threadIdx.x];
        sW[threadIdx.x] = pk2(wv, wv);
    }
    __syncthreads();

    float* lt = g_likc + (size_t)c * NQCP_;
    const float rq = 1.0f / 65535.0f;

    #pragma unroll
    for (int k = 0; k < 4; k++) {
        int ea = e0 + k * 256;
        int eb = ea + 1024;
        float xa = (float)(ea << 3) * rq;
        float xb = (float)(eb << 3) * rq;
        u64 la, lb;
        mlp_dual(pk2(xa - 0.5f, xa + 0.5f), pk2(xb - 0.5f, xb + 0.5f), sW, la, lb);
        float lal, lau, lbl, lbu;
        unpk(la, lal, lau);
        unpk(lb, lbl, lbu);
        lt[ea] = fmaxf(sigf(lau) - sigf(lal), 1e-9f);
        lt[eb] = fmaxf(sigf(lbu) - sigf(lbl), 1e-9f);
    }
    // endpoint e = 8192 (fine q = 65536, one step past 65535)
    if (jb == 3 && threadIdx.x == 0) {
        float xe = 65536.0f * rq;
        u64 le, ldum;
        u64 v = pk2(xe - 0.5f, xe + 0.5f);
        mlp_dual(v, v, sW, le, ldum);
        float ll, lu;
        unpk(le, ll, lu);
        lt[8192] = fmaxf(sigf(lu) - sigf(ll), 1e-9f);
    }
}

// ---------------- kernel: quantize + interpolated gather ----------------
// 1536 blocks = (s,c) planes; 256 threads; 16384 elems/block, 8 pipelined
// chunks of 8 elems/thread. Whole coarse channel table in smem -> no misses.
__global__ void __launch_bounds__(256, 5) k_gather(const float* __restrict__ x,
                                                   float* __restrict__ out) {
    extern __shared__ float sw[];
    const int c = blockIdx.x % C_;
    const int s = blockIdx.x / C_;
    const size_t base = (size_t)s * CHW_ + (size_t)c * HW_;

    const float qs = g_qs[s];
    const float qo = g_qo[s];
    const int t = threadIdx.x;
    const float rq = 1.0f / 65535.0f;

    const float4* xp = reinterpret_cast<const float4*>(x + base);
    float4* ov = reinterpret_cast<float4*>(out + base);
    float4* lv = reinterpret_cast<float4*>(out + NTOT_ + base);

    // prefetch chunk 0 (streaming)
    float4 va = __ldcs(xp + t);
    float4 vb = __ldcs(xp + t + 256);

    // stage full coarse channel table into smem (2050 uint4 = 8200 floats)
    {
        const uint4* src = reinterpret_cast<const uint4*>(g_likc + (size_t)c * NQCP_);
        uint4* dst = reinterpret_cast<uint4*>(sw);
        #pragma unroll
        for (int i = 0; i < 9; i++) {
            int idx = t + i * 256;
            if (idx < 2050) dst[idx] = __ldg(src + idx);
        }
    }
    __syncthreads();

    #pragma unroll
    for (int k = 0; k < 8; k++) {
        float4 v0 = va, v1 = vb;
        if (k < 7) {
            va = __ldcs(xp + (k + 1) * 512 + t);
            vb = __ldcs(xp + (k + 1) * 512 + t + 256);
        }
        int q[8];
        q[0] = min(max(__float2int_rn(fmaf(v0.x, qs, qo)), 0), 65535);
        q[1] = min(max(__float2int_rn(fmaf(v0.y, qs, qo)), 0), 65535);
        q[2] = min(max(__float2int_rn(fmaf(v0.z, qs, qo)), 0), 65535);
        q[3] = min(max(__float2int_rn(fmaf(v0.w, qs, qo)), 0), 65535);
        q[4] = min(max(__float2int_rn(fmaf(v1.x, qs, qo)), 0), 65535);
        q[5] = min(max(__float2int_rn(fmaf(v1.y, qs, qo)), 0), 65535);
        q[6] = min(max(__float2int_rn(fmaf(v1.z, qs, qo)), 0), 65535);
        q[7] = min(max(__float2int_rn(fmaf(v1.w, qs, qo)), 0), 65535);

        float4 o0, o1;
        o0.x = (float)q[0] * rq; o0.y = (float)q[1] * rq;
        o0.z = (float)q[2] * rq; o0.w = (float)q[3] * rq;
        o1.x = (float)q[4] * rq; o1.y = (float)q[5] * rq;
        o1.z = (float)q[6] * rq; o1.w = (float)q[7] * rq;
        __stcs(ov + k * 512 + t, o0);
        __stcs(ov + k * 512 + t + 256, o1);

        float l[8];
        #pragma unroll
        for (int j = 0; j < 8; j++) {
            int i0 = q[j] >> 3;
            float f = (float)(q[j] & 7) * 0.125f;
            float a = sw[i0];
            float b = sw[i0 + 1];
            l[j] = fmaf(b - a, f, a);
        }
        float4 l0, l1;
        l0.x = l[0]; l0.y = l[1]; l0.z = l[2]; l0.w = l[3];
        l1.x = l[4]; l1.y = l[5]; l1.z = l[6]; l1.w = l[7];
        __stcs(lv + k * 512 + t, l0);
        __stcs(lv + k * 512 + t + 256, l1);
    }
}

// ---------------- host launcher (stream fork/join for table||minmax) ---------
extern "C" void kernel_launch(void* const* d_in, const int* in_sizes, int n_in,
                              void* d_out, int out_size) {
    const float* x = (const float*)d_in[0];
    const float *m[5], *bb[5], *ff[4];
    if (n_in >= 15 && in_sizes[2] == 1728) {
        for (int i = 0; i < 5; i++) { m[i]  = (const float*)d_in[1 + i];
                                      bb[i] = (const float*)d_in[6 + i]; }
        for (int i = 0; i < 4; i++)   ff[i] = (const float*)d_in[11 + i];
    } else {
        for (int i = 0; i < 5; i++) { m[i]  = (const float*)d_in[1 + 2 * i];
                                      bb[i] = (const float*)d_in[2 + 2 * i]; }
        for (int i = 0; i < 4; i++)   ff[i] = (const float*)d_in[11 + i];
    }
    float* out = (float*)d_out;

    static int inited = 0;
    static cudaStream_t s2;
    static cudaEvent_t evFork, evJoin;
    if (!inited) {
        cudaFuncSetAttribute(k_gather, cudaFuncAttributeMaxDynamicSharedMemorySize,
                             2050 * 16);
        cudaStreamCreateWithFlags(&s2, cudaStreamNonBlocking);
        cudaEventCreateWithFlags(&evFork, cudaEventDisableTiming);
        cudaEventCreateWithFlags(&evJoin, cudaEventDisableTiming);
        inited = 1;
    }

    // main (capture) stream: prep_w
    k_prep_w<<<1, 192>>>(m[0], bb[0], m[1], bb[1], m[2], bb[2], m[3], bb[3],
                         m[4], bb[4], ff[0], ff[1], ff[2], ff[3]);

    // fork: minmax (DRAM-bound) runs concurrently with tablec (compute-bound)
    cudaEventRecord(evFork, 0);
    cudaStreamWaitEvent(s2, evFork, 0);
    k_minmax<<<2048, 256, 0, s2>>>(x);
    cudaEventRecord(evJoin, s2);

    k_tablec<<<768, 256>>>();

    // join: prep_q needs minmax results; gather needs both
    cudaStreamWaitEvent(0, evJoin, 0);
    k_prep_q<<<1, 32>>>();
    k_gather<<<1536, 256, 2050 * 16>>>(x, out);
}

// round 12
// speedup vs baseline: 1.2719x; 1.0503x over previous
#include <cuda_runtime.h>
#include <math.h>

#define B_    8
#define C_    192
#define HW_   16384
#define CHW_  3145728
#define NTOT_ 25165824
#define NQC_  8193           // coarse table entries used (stride-8 grid + endpoint)
#define NQCP_ 8200           // padded per-channel stride (16B-aligned rows)

typedef unsigned long long u64;

// ---------------- device scratch (no allocations allowed) ----------------
__device__ float g_pmn[B_ * 256];      // per-block partial mins (no atomics)
__device__ float g_pmx[B_ * 256];      // per-block partial maxs
__device__ __align__(16) float g_likc[C_ * NQCP_];  // coarse lik table (~6.3MB)

// ---------------- packed f32x2 helpers (sm_103a FFMA2) ----------------
__device__ __forceinline__ u64 pk2(float a, float b) {
    u64 r; asm("mov.b64 %0, {%1, %2};" : "=l"(r) : "f"(a), "f"(b)); return r;
}
__device__ __forceinline__ void unpk(u64 v, float& a, float& b) {
    asm("mov.b64 {%0, %1}, %2;" : "=f"(a), "=f"(b) : "l"(v));
}
__device__ __forceinline__ u64 fma2(u64 a, u64 b, u64 c) {
    u64 d; asm("fma.rn.f32x2 %0, %1, %2, %3;" : "=l"(d) : "l"(a), "l"(b), "l"(c));
    return d;
}
// gate: y = z + t * tanh(z), tanh via f16x2 MUFU (both lanes in one op)
__device__ __forceinline__ u64 gate2(u64 z, u64 t2) {
    float zl, zu;
    unpk(z, zl, zu);
    unsigned h;
    asm("cvt.rn.f16x2.f32 %0, %1, %2;" : "=r"(h) : "f"(zu), "f"(zl)); // lo=zl, hi=zu
    asm("tanh.approx.f16x2 %0, %1;" : "=r"(h) : "r"(h));
    float tl, tu;
    asm("{\n\t.reg .b16 lo, hi;\n\tmov.b32 {lo, hi}, %2;\n\t"
        "cvt.f32.f16 %0, lo;\n\tcvt.f32.f16 %1, hi;\n\t}"
        : "=f"(tl), "=f"(tu) : "r"(h));
    return fma2(t2, pk2(tl, tu), z);
}
__device__ __forceinline__ float sigf(float v) {
    return __fdividef(1.0f, 1.0f + __expf(-v));
}
__device__ __forceinline__ float softplus_acc(float v) {
    return fmaxf(v, 0.0f) + log1pf(expf(-fabsf(v)));
}

// dual-q packed MLP: va/vb = packed (lower, upper) for two q's.
__device__ __forceinline__ void mlp_dual(u64 va, u64 vb, const u64* __restrict__ sW,
                                         u64& ra, u64& rb) {
    u64 w0 = sW[0], w1 = sW[1], w2 = sW[2];
    u64 bb0 = sW[3], bb1 = sW[4], bb2 = sW[5];
    u64 ya0 = fma2(w0, va, bb0), yb0 = fma2(w0, vb, bb0);
    u64 ya1 = fma2(w1, va, bb1), yb1 = fma2(w1, vb, bb1);
    u64 ya2 = fma2(w2, va, bb2), yb2 = fma2(w2, vb, bb2);
    u64 t0 = sW[6], t1 = sW[7], t2 = sW[8];
    ya0 = gate2(ya0, t0); yb0 = gate2(yb0, t0);
    ya1 = gate2(ya1, t1); yb1 = gate2(yb1, t1);
    ya2 = gate2(ya2, t2); yb2 = gate2(yb2, t2);
    #pragma unroll
    for (int L = 0; L < 3; L++) {
        const u64* Wl = sW + 9 + L * 15;
        u64 m0 = Wl[0], m1 = Wl[1], m2 = Wl[2];
        u64 m3 = Wl[3], m4 = Wl[4], m5 = Wl[5];
        u64 m6 = Wl[6], m7 = Wl[7], m8 = Wl[8];
        u64 c0 = Wl[9], c1 = Wl[10], c2 = Wl[11];
        u64 za0 = fma2(m0, ya0, fma2(m1, ya1, fma2(m2, ya2, c0)));
        u64 zb0 = fma2(m0, yb0, fma2(m1, yb1, fma2(m2, yb2, c0)));
        u64 za1 = fma2(m3, ya0, fma2(m4, ya1, fma2(m5, ya2, c1)));
        u64 zb1 = fma2(m3, yb0, fma2(m4, yb1, fma2(m5, yb2, c1)));
        u64 za2 = fma2(m6, ya0, fma2(m7, ya1, fma2(m8, ya2, c2)));
        u64 zb2 = fma2(m6, yb0, fma2(m7, yb1, fma2(m8, yb2, c2)));
        u64 g0 = Wl[12], g1 = Wl[13], g2 = Wl[14];
        ya0 = gate2(za0, g0); yb0 = gate2(zb0, g0);
        ya1 = gate2(za1, g1); yb1 = gate2(zb1, g1);
        ya2 = gate2(za2, g2); yb2 = gate2(zb2, g2);
    }
    u64 f0 = sW[54], f1 = sW[55], f2 = sW[56], f3 = sW[57];
    ra = fma2(f0, ya0, fma2(f1, ya1, fma2(f2, ya2, f3)));
    rb = fma2(f0, yb0, fma2(f1, yb1, fma2(f2, yb2, f3)));
}

// ---------------- kernel: per-sample min/max partials (no atomics) -----------
__global__ void __launch_bounds__(256) k_minmax_part(const float* __restrict__ x) {
    int s  = blockIdx.x >> 8;
    int jb = blockIdx.x & 255;
    const float4* xp = reinterpret_cast<const float4*>(x + (size_t)s * CHW_) + (size_t)jb * 3072;

    float mn = __int_as_float(0x7f800000);
    float mx = -mn;
    for (int i = threadIdx.x; i < 3072; i += 256) {
        float4 v = __ldcs(xp + i);
        mn = fminf(mn, fminf(fminf(v.x, v.y), fminf(v.z, v.w)));
        mx = fmaxf(mx, fmaxf(fmaxf(v.x, v.y), fmaxf(v.z, v.w)));
    }
    #pragma unroll
    for (int o = 16; o > 0; o >>= 1) {
        mn = fminf(mn, __shfl_xor_sync(0xffffffffu, mn, o));
        mx = fmaxf(mx, __shfl_xor_sync(0xffffffffu, mx, o));
    }
    __shared__ float smn[8], smx[8];
    int w = threadIdx.x >> 5, l = threadIdx.x & 31;
    if (l == 0) { smn[w] = mn; smx[w] = mx; }
    __syncthreads();
    if (threadIdx.x == 0) {
        mn = smn[0]; mx = smx[0];
        #pragma unroll
        for (int i = 1; i < 8; i++) { mn = fminf(mn, smn[i]); mx = fmaxf(mx, smx[i]); }
        g_pmn[blockIdx.x] = mn;
        g_pmx[blockIdx.x] = mx;
    }
}

// ---------------- kernel: coarse table w/ in-block weight prep ----------------
// 768 blocks (4 per channel) x 256 threads; entry e covers fine q = 8e.
// Threads 0-57 transform this channel's raw weights first (no prep kernel).
__global__ void __launch_bounds__(256) k_tablec(
    const float* __restrict__ m0, const float* __restrict__ b0,
    const float* __restrict__ m1, const float* __restrict__ b1,
    const float* __restrict__ m2, const float* __restrict__ b2,
    const float* __restrict__ m3, const float* __restrict__ b3,
    const float* __restrict__ m4, const float* __restrict__ b4,
    const float* __restrict__ f0, const float* __restrict__ f1,
    const float* __restrict__ f2, const float* __restrict__ f3) {
    __shared__ u64 sW[58];
    const int c  = blockIdx.x >> 2;
    const int jb = blockIdx.x & 3;
    const int e0 = (jb << 11) + threadIdx.x;

    {
        int j = threadIdx.x;
        if (j < 58) {
            float v;
            if      (j <  3) v = softplus_acc(m0[c * 3 + j]);
            else if (j <  6) v = b0[c * 3 + j - 3];
            else if (j <  9) v = tanhf(f0[c * 3 + j - 6]);
            else if (j < 18) v = softplus_acc(m1[c * 9 + j - 9]);
            else if (j < 21) v = b1[c * 3 + j - 18];
            else if (j < 24) v = tanhf(f1[c * 3 + j - 21]);
            else if (j < 33) v = softplus_acc(m2[c * 9 + j - 24]);
            else if (j < 36) v = b2[c * 3 + j - 33];
            else if (j < 39) v = tanhf(f2[c * 3 + j - 36]);
            else if (j < 48) v = softplus_acc(m3[c * 9 + j - 39]);
            else if (j < 51) v = b3[c * 3 + j - 48];
            else if (j < 54) v = tanhf(f3[c * 3 + j - 51]);
            else if (j < 57) v = softplus_acc(m4[c * 3 + j - 54]);
            else             v = b4[c];
            sW[j] = pk2(v, v);
        }
    }
    __syncthreads();

    float* lt = g_likc + (size_t)c * NQCP_;
    const float rq = 1.0f / 65535.0f;

    #pragma unroll
    for (int k = 0; k < 4; k++) {
        int ea = e0 + k * 256;
        int eb = ea + 1024;
        float xa = (float)(ea << 3) * rq;
        float xb = (float)(eb << 3) * rq;
        u64 la, lb;
        mlp_dual(pk2(xa - 0.5f, xa + 0.5f), pk2(xb - 0.5f, xb + 0.5f), sW, la, lb);
        float lal, lau, lbl, lbu;
        unpk(la, lal, lau);
        unpk(lb, lbl, lbu);
        lt[ea] = fmaxf(sigf(lau) - sigf(lal), 1e-9f);
        lt[eb] = fmaxf(sigf(lbu) - sigf(lbl), 1e-9f);
    }
    // endpoint e = 8192 (fine q = 65536, one step past 65535)
    if (jb == 3 && threadIdx.x == 0) {
        float xe = 65536.0f * rq;
        u64 le, ldum;
        u64 v = pk2(xe - 0.5f, xe + 0.5f);
        mlp_dual(v, v, sW, le, ldum);
        float ll, lu;
        unpk(le, ll, lu);
        lt[8192] = fmaxf(sigf(lu) - sigf(ll), 1e-9f);
    }
}

// ---------------- kernel: quantize + interpolated gather ----------------
// 1536 blocks = (s,c) planes; 256 threads; 16384 elems/block, 8 pipelined
// chunks of 8 elems/thread. Preamble: reduce sample's 256 minmax partials
// (replaces prep_q kernel). Whole coarse channel table in smem -> no misses.
__global__ void __launch_bounds__(256, 5) k_gather(const float* __restrict__ x,
                                                   float* __restrict__ out) {
    extern __shared__ float sw[];
    __shared__ float sred[16];
    __shared__ float sqp[2];
    const int c = blockIdx.x % C_;
    const int s = blockIdx.x / C_;
    const size_t base = (size_t)s * CHW_ + (size_t)c * HW_;
    const int t = threadIdx.x;
    const float rq = 1.0f / 65535.0f;

    const float4* xp = reinterpret_cast<const float4*>(x + base);
    float4* ov = reinterpret_cast<float4*>(out + base);
    float4* lv = reinterpret_cast<float4*>(out + NTOT_ + base);

    // prefetch chunk 0 (streaming)
    float4 va = __ldcs(xp + t);
    float4 vb = __ldcs(xp + t + 256);

    // reduce this sample's 256 minmax partials (L2-hot, 512 loads)
    {
        float pmn = g_pmn[s * 256 + t];
        float pmx = g_pmx[s * 256 + t];
        #pragma unroll
        for (int o = 16; o > 0; o >>= 1) {
            pmn = fminf(pmn, __shfl_xor_sync(0xffffffffu, pmn, o));
            pmx = fmaxf(pmx, __shfl_xor_sync(0xffffffffu, pmx, o));
        }
        int w = t >> 5, l = t & 31;
        if (l == 0) { sred[w] = pmn; sred[8 + w] = pmx; }
    }

    // stage full coarse channel table into smem (2050 uint4 = 8200 floats)
    {
        const uint4* src = reinterpret_cast<const uint4*>(g_likc + (size_t)c * NQCP_);
        uint4* dst = reinterpret_cast<uint4*>(sw);
        #pragma unroll
        for (int i = 0; i < 9; i++) {
            int idx = t + i * 256;
            if (idx < 2050) dst[idx] = __ldg(src + idx);
        }
    }
    __syncthreads();
    if (t == 0) {
        float mn = sred[0], mx = sred[8];
        #pragma unroll
        for (int i = 1; i < 8; i++) { mn = fminf(mn, sred[i]); mx = fmaxf(mx, sred[8 + i]); }
        float denom = (mx - mn) + 1e-12f;
        float qsv = __fdiv_rn(65535.0f, denom);   // identical arithmetic to prep_q
        sqp[0] = qsv;
        sqp[1] = -mn * qsv;
    }
    __syncthreads();
    const float qs = sqp[0];
    const float qo = sqp[1];

    #pragma unroll
    for (int k = 0; k < 8; k++) {
        float4 v0 = va, v1 = vb;
        if (k < 7) {
            va = __ldcs(xp + (k + 1) * 512 + t);
            vb = __ldcs(xp + (k + 1) * 512 + t + 256);
        }
        int q[8];
        q[0] = min(max(__float2int_rn(fmaf(v0.x, qs, qo)), 0), 65535);
        q[1] = min(max(__float2int_rn(fmaf(v0.y, qs, qo)), 0), 65535);
        q[2] = min(max(__float2int_rn(fmaf(v0.z, qs, qo)), 0), 65535);
        q[3] = min(max(__float2int_rn(fmaf(v0.w, qs, qo)), 0), 65535);
        q[4] = min(max(__float2int_rn(fmaf(v1.x, qs, qo)), 0), 65535);
        q[5] = min(max(__float2int_rn(fmaf(v1.y, qs, qo)), 0), 65535);
        q[6] = min(max(__float2int_rn(fmaf(v1.z, qs, qo)), 0), 65535);
        q[7] = min(max(__float2int_rn(fmaf(v1.w, qs, qo)), 0), 65535);

        float4 o0, o1;
        o0.x = (float)q[0] * rq; o0.y = (float)q[1] * rq;
        o0.z = (float)q[2] * rq; o0.w = (float)q[3] * rq;
        o1.x = (float)q[4] * rq; o1.y = (float)q[5] * rq;
        o1.z = (float)q[6] * rq; o1.w = (float)q[7] * rq;
        __stcs(ov + k * 512 + t, o0);
        __stcs(ov + k * 512 + t + 256, o1);

        float l[8];
        #pragma unroll
        for (int j = 0; j < 8; j++) {
            int i0 = q[j] >> 3;
            float f = (float)(q[j] & 7) * 0.125f;
            float a = sw[i0];
            float b = sw[i0 + 1];
            l[j] = fmaf(b - a, f, a);
        }
        float4 l0, l1;
        l0.x = l[0]; l0.y = l[1]; l0.z = l[2]; l0.w = l[3];
        l1.x = l[4]; l1.y = l[5]; l1.z = l[6]; l1.w = l[7];
        __stcs(lv + k * 512 + t, l0);
        __stcs(lv + k * 512 + t + 256, l1);
    }
}

// ---------------- host launcher (3 kernels, fork at t=0) ----------------
extern "C" void kernel_launch(void* const* d_in, const int* in_sizes, int n_in,
                              void* d_out, int out_size) {
    const float* x = (const float*)d_in[0];
    const float *m[5], *bb[5], *ff[4];
    if (n_in >= 15 && in_sizes[2] == 1728) {
        for (int i = 0; i < 5; i++) { m[i]  = (const float*)d_in[1 + i];
                                      bb[i] = (const float*)d_in[6 + i]; }
        for (int i = 0; i < 4; i++)   ff[i] = (const float*)d_in[11 + i];
    } else {
        for (int i = 0; i < 5; i++) { m[i]  = (const float*)d_in[1 + 2 * i];
                                      bb[i] = (const float*)d_in[2 + 2 * i]; }
        for (int i = 0; i < 4; i++)   ff[i] = (const float*)d_in[11 + i];
    }
    float* out = (float*)d_out;

    static int inited = 0;
    static cudaStream_t s2;
    static cudaEvent_t evFork, evJoin;
    if (!inited) {
        cudaFuncSetAttribute(k_gather, cudaFuncAttributeMaxDynamicSharedMemorySize,
                             2050 * 16);
        cudaStreamCreateWithFlags(&s2, cudaStreamNonBlocking);
        cudaEventCreateWithFlags(&evFork, cudaEventDisableTiming);
        cudaEventCreateWithFlags(&evJoin, cudaEventDisableTiming);
        inited = 1;
    }

    // fork immediately: minmax partials (DRAM) || coarse table (compute)
    cudaEventRecord(evFork, 0);
    cudaStreamWaitEvent(s2, evFork, 0);
    k_minmax_part<<<2048, 256, 0, s2>>>(x);
    cudaEventRecord(evJoin, s2);

    k_tablec<<<768, 256>>>(m[0], bb[0], m[1], bb[1], m[2], bb[2], m[3], bb[3],
                           m[4], bb[4], ff[0], ff[1], ff[2], ff[3]);

    // join: gather needs both table and minmax partials
    cudaStreamWaitEvent(0, evJoin, 0);
    k_gather<<<1536, 256, 2050 * 16>>>(x, out);
}